// round 1
// baseline (speedup 1.0000x reference)
#include <cuda_runtime.h>
#include <cstdint>
#include <math.h>

#define BB 32768
#define DD 256
#define NN 8192

// Scratch (allocation-free rule: __device__ globals)
__device__ float g_xT[DD * BB];   // x transposed, [k][b]   (32 MB)
__device__ float g_eT[DD * NN];   // normalized e transposed, [k][n] (8 MB)
__device__ int   g_idx[BB];
__device__ float g_commit[BB];

__device__ __forceinline__ unsigned int ford(float f) {
    unsigned int u = __float_as_uint(f);
    return (u & 0x80000000u) ? ~u : (u | 0x80000000u);
}

// ---------------------------------------------------------------------------
// Kernel A: normalize embedding rows (matches F.normalize: v / max(||v||,1e-12))
// and write transposed into g_eT[k][n]. One warp per row.
// ---------------------------------------------------------------------------
__global__ void norm_e_kernel(const float* __restrict__ e) {
    int w = threadIdx.x >> 5;
    int lane = threadIdx.x & 31;
    int n = blockIdx.x * 8 + w;
    float v[8];
    float ss = 0.f;
#pragma unroll
    for (int j = 0; j < 8; j++) {
        v[j] = e[n * DD + j * 32 + lane];
        ss += v[j] * v[j];
    }
#pragma unroll
    for (int o = 16; o > 0; o >>= 1) ss += __shfl_xor_sync(0xffffffffu, ss, o);
    float inv = 1.0f / fmaxf(sqrtf(ss), 1e-12f);
#pragma unroll
    for (int j = 0; j < 8; j++)
        g_eT[(j * 32 + lane) * NN + n] = v[j] * inv;
}

// ---------------------------------------------------------------------------
// Kernel A2: transpose x (B x D) -> g_xT (D x B). Classic 32x32 smem tiles.
// ---------------------------------------------------------------------------
__global__ void transpose_x_kernel(const float* __restrict__ x) {
    __shared__ float tile[32][33];
    int bx = blockIdx.x, by = blockIdx.y;
    int txi = threadIdx.x, tyi = threadIdx.y;
#pragma unroll
    for (int j = 0; j < 4; j++)
        tile[tyi + j * 8][txi] = x[(bx * 32 + tyi + j * 8) * DD + by * 32 + txi];
    __syncthreads();
#pragma unroll
    for (int j = 0; j < 4; j++)
        g_xT[(by * 32 + tyi + j * 8) * BB + bx * 32 + txi] = tile[txi][tyi + j * 8];
}

// ---------------------------------------------------------------------------
// Kernel B: fused GEMM + argmax.  s[b][n] = x_b . e_hat_n,  per-row argmax.
// Block tile: 128 rows x full N sweep (128-col chunks). Thread tile 8x8 via
// packed fma.rn.f32x2 (8 rows x 4 f32x2 accumulators). 256 threads, 256 blocks.
// ---------------------------------------------------------------------------
__global__ void __launch_bounds__(256) argmax_kernel() {
    __shared__ float4 xs[32][32];   // [k][row/4], 128 rows
    __shared__ float4 es[32][32];   // [k][col/4], 128 cols
    int tid = threadIdx.x;
    int tx = tid & 15;              // col group
    int ty = tid >> 4;              // row group
    int rb = blockIdx.x * 128;

    float bestv[8];
    int besti[8];
#pragma unroll
    for (int i = 0; i < 8; i++) { bestv[i] = -3.4e38f; besti[i] = 0; }

    for (int nc = 0; nc < NN; nc += 128) {
        unsigned long long acc[8][4];
#pragma unroll
        for (int i = 0; i < 8; i++)
#pragma unroll
            for (int p = 0; p < 4; p++) acc[i][p] = 0ull;  // (0.f, 0.f)

        for (int kk = 0; kk < DD; kk += 32) {
            __syncthreads();
#pragma unroll
            for (int i2 = 0; i2 < 4; i2++) {
                int q = tid + i2 * 256;
                int k = q >> 5, c4 = q & 31;
                xs[k][c4] = ((const float4*)(&g_xT[(kk + k) * BB + rb]))[c4];
                es[k][c4] = ((const float4*)(&g_eT[(kk + k) * NN + nc]))[c4];
            }
            __syncthreads();
#pragma unroll
            for (int k = 0; k < 32; k++) {
                float4 a0 = xs[k][ty * 2];
                float4 a1 = xs[k][ty * 2 + 1];
                float4 b0 = es[k][tx];          // cols tx*4 .. tx*4+3
                float4 b1 = es[k][16 + tx];     // cols 64+tx*4 .. +3
                unsigned long long bb[4];
                asm("mov.b64 %0, {%1, %2};" : "=l"(bb[0]) : "f"(b0.x), "f"(b0.y));
                asm("mov.b64 %0, {%1, %2};" : "=l"(bb[1]) : "f"(b0.z), "f"(b0.w));
                asm("mov.b64 %0, {%1, %2};" : "=l"(bb[2]) : "f"(b1.x), "f"(b1.y));
                asm("mov.b64 %0, {%1, %2};" : "=l"(bb[3]) : "f"(b1.z), "f"(b1.w));
                float av[8] = {a0.x, a0.y, a0.z, a0.w, a1.x, a1.y, a1.z, a1.w};
#pragma unroll
                for (int i = 0; i < 8; i++) {
                    unsigned long long aa;
                    asm("mov.b64 %0, {%1, %1};" : "=l"(aa) : "f"(av[i]));
#pragma unroll
                    for (int p = 0; p < 4; p++) {
                        asm("fma.rn.f32x2 %0, %1, %2, %0;"
                            : "+l"(acc[i][p]) : "l"(aa), "l"(bb[p]));
                    }
                }
            }
        }
        // per-thread running argmax update (strictly > keeps earliest index)
#pragma unroll
        for (int i = 0; i < 8; i++) {
#pragma unroll
            for (int p = 0; p < 4; p++) {
                float lo, hi;
                asm("mov.b64 {%0, %1}, %2;" : "=f"(lo), "=f"(hi) : "l"(acc[i][p]));
                int base = (p < 2) ? (nc + tx * 4 + p * 2)
                                   : (nc + 64 + tx * 4 + (p - 2) * 2);
                if (lo > bestv[i]) { bestv[i] = lo; besti[i] = base; }
                if (hi > bestv[i]) { bestv[i] = hi; besti[i] = base + 1; }
            }
        }
    }

    // cross-lane argmax reduce over the 16 lanes sharing rows.
    // key packs (orderable sim, inverted idx): max key == max sim, tie -> min idx
#pragma unroll
    for (int i = 0; i < 8; i++) {
        unsigned long long key =
            ((unsigned long long)ford(bestv[i]) << 32) |
            (unsigned long long)(unsigned)(0x7fffffff - besti[i]);
#pragma unroll
        for (int o = 8; o > 0; o >>= 1) {
            unsigned long long k2 = __shfl_xor_sync(0xffffffffu, key, o);
            if (k2 > key) key = k2;
        }
        if (tx == 0)
            g_idx[rb + ty * 8 + i] = 0x7fffffff - (int)(key & 0xffffffffu);
    }
}

// ---------------------------------------------------------------------------
// Kernel C: per-row epilogue. Gather chosen codeword, projection, x_q, scalar,
// per-row (1 - commit). One block (256 thr) per row.
// ---------------------------------------------------------------------------
__global__ void epilogue_kernel(const float* __restrict__ x,
                                const float* __restrict__ e,
                                float* __restrict__ out) {
    int b = blockIdx.x;
    int t = threadIdx.x;
    int idx = g_idx[b];
    float xv = x[b * DD + t];
    float cv = e[idx * DD + t];
    float s1 = xv * cv, s2 = cv * cv, s3 = xv * xv;
#pragma unroll
    for (int o = 16; o > 0; o >>= 1) {
        s1 += __shfl_xor_sync(0xffffffffu, s1, o);
        s2 += __shfl_xor_sync(0xffffffffu, s2, o);
        s3 += __shfl_xor_sync(0xffffffffu, s3, o);
    }
    __shared__ float r1[8], r2[8], r3[8];
    __shared__ float bc[3];
    int w = t >> 5, lane = t & 31;
    if (lane == 0) { r1[w] = s1; r2[w] = s2; r3[w] = s3; }
    __syncthreads();
    if (t == 0) {
        float d = 0.f, c = 0.f, xx = 0.f;
#pragma unroll
        for (int i = 0; i < 8; i++) { d += r1[i]; c += r2[i]; xx += r3[i]; }
        bc[0] = d; bc[1] = c; bc[2] = xx;
    }
    __syncthreads();
    float dot = bc[0], csq = bc[1], xsq = bc[2];
    float scalar = dot / (csq + 1e-8f);
    float proj = scalar * cv;
    out[b * DD + t] = xv + (proj - xv);   // straight-through x_q
    if (t == 0) {
        float pn = fabsf(scalar) * sqrtf(csq);          // ||proj||
        float commit = (scalar * dot) /
                       (fmaxf(pn, 1e-8f) * fmaxf(sqrtf(xsq), 1e-8f));
        g_commit[b] = 1.0f - commit;
        out[BB * DD + 1 + b] = (float)idx;              // indices (as f32)
        out[BB * DD + 1 + BB + b] = scalar;             // scalar[:,0]
    }
}

// ---------------------------------------------------------------------------
// Kernel D: deterministic reduction of (1 - commit) -> loss
// ---------------------------------------------------------------------------
__global__ void loss_kernel(float* __restrict__ out) {
    __shared__ float sh[256];
    float s = 0.f;
    for (int i = threadIdx.x; i < BB; i += 256) s += g_commit[i];
    sh[threadIdx.x] = s;
    __syncthreads();
    for (int o = 128; o > 0; o >>= 1) {
        if (threadIdx.x < o) sh[threadIdx.x] += sh[threadIdx.x + o];
        __syncthreads();
    }
    if (threadIdx.x == 0) out[BB * DD] = 0.25f * sh[0] / (float)BB;
}

// ---------------------------------------------------------------------------
extern "C" void kernel_launch(void* const* d_in, const int* in_sizes, int n_in,
                              void* d_out, int out_size) {
    const float* x = (const float*)d_in[0];       // (B, D)
    const float* e = (const float*)d_in[1];       // (N, D)
    float* out = (float*)d_out;

    norm_e_kernel<<<NN / 8, 256>>>(e);
    transpose_x_kernel<<<dim3(BB / 32, DD / 32), dim3(32, 8)>>>(x);
    argmax_kernel<<<BB / 128, 256>>>();
    epilogue_kernel<<<BB, 256>>>(x, e, out);
    loss_kernel<<<1, 256>>>(out);
}

// round 3
// speedup vs baseline: 6.6115x; 6.6115x over previous
#include <cuda_runtime.h>
#include <cuda_bf16.h>
#include <cstdint>
#include <math.h>

#define BB 32768
#define DD 256
#define NN 8192

// ---------------- scratch (__device__ globals; no allocation allowed) -------
__device__ __nv_bfloat16 g_xb[(size_t)BB * DD];    // bf16(x)           16 MB
__device__ __nv_bfloat16 g_eb[(size_t)NN * DD];    // bf16(e_hat)        4 MB
__device__ float         g_ehat[(size_t)NN * DD];  // e_hat fp32         8 MB
__device__ __nv_bfloat16 g_sims[(size_t)BB * NN];  // noisy sims       512 MB
__device__ float g_xnorm[BB];
__device__ float g_rowmax[BB];
__device__ float g_commit[BB];

// ---------------- helpers ---------------------------------------------------
__device__ __forceinline__ unsigned ford(float f) {
    unsigned u = __float_as_uint(f);
    return (u & 0x80000000u) ? ~u : (u | 0x80000000u);
}
__device__ __forceinline__ float unford(unsigned u) {
    unsigned v = (u & 0x80000000u) ? (u & 0x7fffffffu) : ~u;
    return __uint_as_float(v);
}
__device__ __forceinline__ uint32_t s2u(const void* p) {
    uint32_t a;
    asm("{ .reg .u64 t; cvta.to.shared.u64 t, %1; cvt.u32.u64 %0, t; }"
        : "=r"(a) : "l"(p));
    return a;
}
// smem tile layout: 128 rows x 256 bf16 (512 B/row), 16B units XOR-swizzled
__device__ __forceinline__ uint32_t soff(int row, int u) {
    return (uint32_t)(row * 512 + ((u ^ (row & 7)) << 4));
}
__device__ __forceinline__ void cpa16(uint32_t s, const void* g) {
    asm volatile("cp.async.cg.shared.global [%0], [%1], 16;" :: "r"(s), "l"(g));
}
#define CPA_COMMIT() asm volatile("cp.async.commit_group;" ::: "memory")
#define CPA_WAIT0()  asm volatile("cp.async.wait_group 0;" ::: "memory")

#define LDSM4(r0, r1, r2, r3, addr) \
    asm volatile("ldmatrix.sync.aligned.m8n8.x4.shared.b16 {%0,%1,%2,%3}, [%4];" \
                 : "=r"(r0), "=r"(r1), "=r"(r2), "=r"(r3) : "r"(addr))

#define MMA16816(d, a0, a1, a2, a3, b0, b1) \
    asm volatile("mma.sync.aligned.m16n8k16.row.col.f32.bf16.bf16.f32 " \
                 "{%0,%1,%2,%3}, {%4,%5,%6,%7}, {%8,%9}, {%0,%1,%2,%3};" \
                 : "+f"((d)[0]), "+f"((d)[1]), "+f"((d)[2]), "+f"((d)[3]) \
                 : "r"(a0), "r"(a1), "r"(a2), "r"(a3), "r"(b0), "r"(b1))

// ---------------- prep kernels ---------------------------------------------
__global__ void prep_x_kernel(const float* __restrict__ x) {
    int w = threadIdx.x >> 5, lane = threadIdx.x & 31;
    int b = blockIdx.x * 8 + w;
    float ss = 0.f;
#pragma unroll
    for (int j = 0; j < 8; j++) {
        float v = x[(size_t)b * DD + j * 32 + lane];
        ss += v * v;
        g_xb[(size_t)b * DD + j * 32 + lane] = __float2bfloat16(v);
    }
#pragma unroll
    for (int o = 16; o > 0; o >>= 1) ss += __shfl_xor_sync(0xffffffffu, ss, o);
    if (lane == 0) g_xnorm[b] = sqrtf(ss);
}

__global__ void prep_e_kernel(const float* __restrict__ e) {
    int w = threadIdx.x >> 5, lane = threadIdx.x & 31;
    int n = blockIdx.x * 8 + w;
    float v[8];
    float ss = 0.f;
#pragma unroll
    for (int j = 0; j < 8; j++) {
        v[j] = e[(size_t)n * DD + j * 32 + lane];
        ss += v[j] * v[j];
    }
#pragma unroll
    for (int o = 16; o > 0; o >>= 1) ss += __shfl_xor_sync(0xffffffffu, ss, o);
    float inv = 1.f / fmaxf(sqrtf(ss), 1e-12f);
#pragma unroll
    for (int j = 0; j < 8; j++) {
        float h = v[j] * inv;
        g_ehat[(size_t)n * DD + j * 32 + lane] = h;
        g_eb[(size_t)n * DD + j * 32 + lane] = __float2bfloat16(h);
    }
}

// ---------------- HMMA bf16 GEMM: sims (bf16) + per-row fp32 max -----------
// smem: A 64KB | B0 64KB | B1 64KB | rowmax 512B  => 197120 B dynamic
#define SM_B0 65536
#define SM_B1 131072
#define SM_RM 196608
#define DYN_SMEM (196608 + 512)

__global__ void __launch_bounds__(256) gemm_kernel() {
    extern __shared__ char sm[];
    uint32_t sA = s2u(sm);
    int tid = threadIdx.x, wid = tid >> 5, lane = tid & 31;
    int rb = blockIdx.x * 128;
    unsigned* rowmax_s = (unsigned*)(sm + SM_RM);
    if (tid < 128) rowmax_s[tid] = 0u;

    // prologue: A tile (rows rb..rb+127) + B chunk 0
#pragma unroll
    for (int i = 0; i < 16; i++) {
        int q = tid + (i << 8);
        int row = q >> 5, u = q & 31;
        cpa16(sA + soff(row, u), g_xb + (size_t)(rb + row) * DD + u * 8);
        cpa16(sA + SM_B0 + soff(row, u), g_eb + (size_t)row * DD + u * 8);
    }
    CPA_COMMIT();
    CPA_WAIT0();
    __syncthreads();

    int wm = wid >> 2, wn = wid & 3;
    int g = lane >> 2, cpair = (lane & 3) * 2;
    float mx[8];
#pragma unroll
    for (int s = 0; s < 8; s++) mx[s] = -3.4e38f;

    // per-lane ldmatrix row/ku components
    int la7 = lane & 7;
    int rowA_c = wm * 64 + la7 + ((lane >> 3) & 1) * 8;  // + mi*16
    int kuA_c = (lane >> 4);
    int rowB_c = wn * 32 + la7 + ((lane >> 4) & 1) * 8;  // + h*16
    int kuB_c = (lane >> 3) & 1;

    for (int t = 0; t < 64; t++) {
        uint32_t sBc = sA + ((t & 1) ? SM_B1 : SM_B0);
        if (t < 63) {
            uint32_t sBn = sA + ((t & 1) ? SM_B0 : SM_B1);
            const __nv_bfloat16* gsrc = g_eb + (size_t)(t + 1) * 128 * DD;
#pragma unroll
            for (int i = 0; i < 16; i++) {
                int q = tid + (i << 8);
                int row = q >> 5, u = q & 31;
                cpa16(sBn + soff(row, u), gsrc + (size_t)row * DD + u * 8);
            }
            CPA_COMMIT();
        }

        float acc[4][4][4];
#pragma unroll
        for (int mi = 0; mi < 4; mi++)
#pragma unroll
            for (int ni = 0; ni < 4; ni++)
#pragma unroll
                for (int r = 0; r < 4; r++) acc[mi][ni][r] = 0.f;

#pragma unroll
        for (int ks = 0; ks < 16; ks++) {
            int kb = ks * 2;
            uint32_t b[4][2];
#pragma unroll
            for (int h = 0; h < 2; h++) {
                int rowB = rowB_c + h * 16;
                uint32_t addr = sBc + soff(rowB, kb + kuB_c);
                LDSM4(b[h * 2][0], b[h * 2][1], b[h * 2 + 1][0], b[h * 2 + 1][1],
                      addr);
            }
#pragma unroll
            for (int mi = 0; mi < 4; mi++) {
                int rowA = rowA_c + mi * 16;
                uint32_t addr = sA + soff(rowA, kb + kuA_c);
                uint32_t a0, a1, a2, a3;
                LDSM4(a0, a1, a2, a3, addr);
#pragma unroll
                for (int ni = 0; ni < 4; ni++)
                    MMA16816(acc[mi][ni], a0, a1, a2, a3, b[ni][0], b[ni][1]);
            }
        }

        // epilogue: bf16 store + running max
        size_t ncol = (size_t)t * 128 + wn * 32 + cpair;
#pragma unroll
        for (int mi = 0; mi < 4; mi++) {
            size_t r0 = (size_t)(rb + wm * 64 + mi * 16 + g);
            size_t r1 = r0 + 8;
            float m0 = mx[mi * 2], m1 = mx[mi * 2 + 1];
#pragma unroll
            for (int ni = 0; ni < 4; ni++) {
                float d0 = acc[mi][ni][0], d1 = acc[mi][ni][1];
                float d2 = acc[mi][ni][2], d3 = acc[mi][ni][3];
                __nv_bfloat162 p0 = __floats2bfloat162_rn(d0, d1);
                __nv_bfloat162 p1 = __floats2bfloat162_rn(d2, d3);
                *(uint32_t*)(g_sims + r0 * NN + ncol + ni * 8) = *(uint32_t*)&p0;
                *(uint32_t*)(g_sims + r1 * NN + ncol + ni * 8) = *(uint32_t*)&p1;
                m0 = fmaxf(m0, fmaxf(d0, d1));
                m1 = fmaxf(m1, fmaxf(d2, d3));
            }
            mx[mi * 2] = m0;
            mx[mi * 2 + 1] = m1;
        }

        if (t < 63) {
            CPA_WAIT0();
            __syncthreads();
        }
    }

    // reduce maxes across the 4 lanes of each quad (same rows), then smem
#pragma unroll
    for (int s = 0; s < 8; s++) {
        float m = mx[s];
        m = fmaxf(m, __shfl_xor_sync(0xffffffffu, m, 1));
        m = fmaxf(m, __shfl_xor_sync(0xffffffffu, m, 2));
        mx[s] = m;
    }
    if ((lane & 3) == 0) {
#pragma unroll
        for (int s = 0; s < 8; s++) {
            int row = wm * 64 + (s >> 1) * 16 + (s & 1) * 8 + g;
            atomicMax(&rowmax_s[row], ford(mx[s]));
        }
    }
    __syncthreads();
    if (tid < 128) g_rowmax[rb + tid] = unford(rowmax_s[tid]);
}

// ---------------- per-row candidate scan + exact rescore + epilogue --------
__global__ void __launch_bounds__(256) scan_kernel(const float* __restrict__ x,
                                                   const float* __restrict__ e,
                                                   float* __restrict__ out) {
    __shared__ float xs[256];
    __shared__ __nv_bfloat16 srow[8192];
    __shared__ float red[8];
    __shared__ int clist[256];
    __shared__ int ccnt;
    __shared__ float bestd_s;
    __shared__ int bestn_s;
    int b = blockIdx.x, t = threadIdx.x, w = t >> 5, lane = t & 31;

    xs[t] = x[(size_t)b * DD + t];
    const uint4* gs = (const uint4*)(g_sims + (size_t)b * NN);
    uint4* s4 = (uint4*)srow;
#pragma unroll
    for (int i = 0; i < 4; i++) s4[t + i * 256] = gs[t + i * 256];
    if (t == 0) { bestd_s = -3.4e38f; bestn_s = 0; }
    float xn = g_xnorm[b], rmx = g_rowmax[b];
    // margin: bf16-input dot error (2 * 2^-9 * ||x||, both entries) +
    //         bf16 storage rounding + slack
    float thresh = rmx - (0.01f * xn + 0.01f * fabsf(rmx) + 0.02f);
    __syncthreads();

    for (int base = 0; base < NN; base += 256) {
        if (t == 0) ccnt = 0;
        __syncthreads();
        float s = __bfloat162float(srow[base + t]);
        if (s >= thresh) { int p = atomicAdd(&ccnt, 1); clist[p] = base + t; }
        __syncthreads();
        int L = ccnt;
        for (int i = 0; i < L; i++) {
            int n = clist[i];
            float p = xs[t] * g_ehat[(size_t)n * DD + t];
#pragma unroll
            for (int o = 16; o > 0; o >>= 1)
                p += __shfl_xor_sync(0xffffffffu, p, o);
            if (lane == 0) red[w] = p;
            __syncthreads();
            if (t == 0) {
                float d = ((red[0] + red[1]) + (red[2] + red[3])) +
                          ((red[4] + red[5]) + (red[6] + red[7]));
                if (d > bestd_s || (d == bestd_s && n < bestn_s)) {
                    bestd_s = d; bestn_s = n;
                }
            }
            __syncthreads();
        }
    }
    int idx = bestn_s;

    // fused epilogue (same math as the passing round-1 kernel)
    float xv = xs[t];
    float cv = e[(size_t)idx * DD + t];
    float s1 = xv * cv, s2 = cv * cv, s3 = xv * xv;
#pragma unroll
    for (int o = 16; o > 0; o >>= 1) {
        s1 += __shfl_xor_sync(0xffffffffu, s1, o);
        s2 += __shfl_xor_sync(0xffffffffu, s2, o);
        s3 += __shfl_xor_sync(0xffffffffu, s3, o);
    }
    __shared__ float r1[8], r2[8], r3[8];
    __shared__ float bc[3];
    if (lane == 0) { r1[w] = s1; r2[w] = s2; r3[w] = s3; }
    __syncthreads();
    if (t == 0) {
        float d = 0.f, c = 0.f, xx = 0.f;
#pragma unroll
        for (int i = 0; i < 8; i++) { d += r1[i]; c += r2[i]; xx += r3[i]; }
        bc[0] = d; bc[1] = c; bc[2] = xx;
    }
    __syncthreads();
    float dot = bc[0], csq = bc[1], xsq = bc[2];
    float scalar = dot / (csq + 1e-8f);
    float proj = scalar * cv;
    out[(size_t)b * DD + t] = xv + (proj - xv);
    if (t == 0) {
        float pn = fabsf(scalar) * sqrtf(csq);
        float commit = (scalar * dot) /
                       (fmaxf(pn, 1e-8f) * fmaxf(sqrtf(xsq), 1e-8f));
        g_commit[b] = 1.0f - commit;
        out[(size_t)BB * DD + 1 + b] = (float)idx;
        out[(size_t)BB * DD + 1 + BB + b] = scalar;
    }
}

// ---------------- loss -----------------------------------------------------
__global__ void loss_kernel(float* __restrict__ out) {
    __shared__ float sh[256];
    float s = 0.f;
    for (int i = threadIdx.x; i < BB; i += 256) s += g_commit[i];
    sh[threadIdx.x] = s;
    __syncthreads();
    for (int o = 128; o > 0; o >>= 1) {
        if (threadIdx.x < o) sh[threadIdx.x] += sh[threadIdx.x + o];
        __syncthreads();
    }
    if (threadIdx.x == 0) out[(size_t)BB * DD] = 0.25f * sh[0] / (float)BB;
}

// ---------------------------------------------------------------------------
extern "C" void kernel_launch(void* const* d_in, const int* in_sizes, int n_in,
                              void* d_out, int out_size) {
    const float* x = (const float*)d_in[0];
    const float* e = (const float*)d_in[1];
    float* out = (float*)d_out;

    cudaFuncSetAttribute(gemm_kernel,
                         cudaFuncAttributeMaxDynamicSharedMemorySize, DYN_SMEM);
    prep_x_kernel<<<BB / 8, 256>>>(x);
    prep_e_kernel<<<NN / 8, 256>>>(e);
    gemm_kernel<<<BB / 128, 256, DYN_SMEM>>>();
    scan_kernel<<<BB, 256>>>(x, e, out);
    loss_kernel<<<1, 256>>>(out);
}

// round 4
// speedup vs baseline: 7.4764x; 1.1308x over previous
#include <cuda_runtime.h>
#include <cuda_bf16.h>
#include <cstdint>
#include <math.h>

#define BB 32768
#define DD 256
#define NN 8192
#define CAP 128

// ---------------- scratch (__device__ globals; no allocation allowed) -------
__device__ __nv_bfloat16 g_xb[(size_t)BB * DD];    // bf16(x)          16 MB
__device__ __nv_bfloat16 g_eb[(size_t)NN * DD];    // bf16(e_hat)       4 MB
__device__ float         g_ehat[(size_t)NN * DD];  // e_hat fp32        8 MB
__device__ int   g_cand[(size_t)BB * CAP];         // candidate cols   16 MB
__device__ int   g_ccnt[BB];
__device__ float g_xnorm[BB];
__device__ float g_commit[BB];

// ---------------- helpers ---------------------------------------------------
__device__ __forceinline__ unsigned ford(float f) {
    unsigned u = __float_as_uint(f);
    return (u & 0x80000000u) ? ~u : (u | 0x80000000u);
}
__device__ __forceinline__ float unford(unsigned u) {
    unsigned v = (u & 0x80000000u) ? (u & 0x7fffffffu) : ~u;
    return __uint_as_float(v);
}
__device__ __forceinline__ uint32_t s2u(const void* p) {
    uint32_t a;
    asm("{ .reg .u64 t; cvta.to.shared.u64 t, %1; cvt.u32.u64 %0, t; }"
        : "=r"(a) : "l"(p));
    return a;
}
// smem tile layout: 128 rows x 256 bf16 (512 B/row), 16B units XOR-swizzled
__device__ __forceinline__ uint32_t soff(int row, int u) {
    return (uint32_t)(row * 512 + ((u ^ (row & 7)) << 4));
}
__device__ __forceinline__ void cpa16(uint32_t s, const void* g) {
    asm volatile("cp.async.cg.shared.global [%0], [%1], 16;" :: "r"(s), "l"(g));
}
#define CPA_COMMIT() asm volatile("cp.async.commit_group;" ::: "memory")
#define CPA_WAIT0()  asm volatile("cp.async.wait_group 0;" ::: "memory")

#define LDSM4(r0, r1, r2, r3, addr) \
    asm volatile("ldmatrix.sync.aligned.m8n8.x4.shared.b16 {%0,%1,%2,%3}, [%4];" \
                 : "=r"(r0), "=r"(r1), "=r"(r2), "=r"(r3) : "r"(addr))

#define MMA16816(d, a0, a1, a2, a3, b0, b1) \
    asm volatile("mma.sync.aligned.m16n8k16.row.col.f32.bf16.bf16.f32 " \
                 "{%0,%1,%2,%3}, {%4,%5,%6,%7}, {%8,%9}, {%0,%1,%2,%3};" \
                 : "+f"((d)[0]), "+f"((d)[1]), "+f"((d)[2]), "+f"((d)[3]) \
                 : "r"(a0), "r"(a1), "r"(a2), "r"(a3), "r"(b0), "r"(b1))

__device__ __forceinline__ void append_cand(int row, int col) {
    int p = atomicAdd(&g_ccnt[row], 1);
    if (p < CAP) g_cand[(size_t)row * CAP + p] = col;
}

// ---------------- prep kernels ---------------------------------------------
__global__ void prep_x_kernel(const float* __restrict__ x) {
    int w = threadIdx.x >> 5, lane = threadIdx.x & 31;
    int b = blockIdx.x * 8 + w;
    float ss = 0.f;
#pragma unroll
    for (int j = 0; j < 8; j++) {
        float v = x[(size_t)b * DD + j * 32 + lane];
        ss += v * v;
        g_xb[(size_t)b * DD + j * 32 + lane] = __float2bfloat16(v);
    }
#pragma unroll
    for (int o = 16; o > 0; o >>= 1) ss += __shfl_xor_sync(0xffffffffu, ss, o);
    if (lane == 0) {
        g_xnorm[b] = sqrtf(ss);
        g_ccnt[b] = 0;                       // re-zero every launch
    }
}

__global__ void prep_e_kernel(const float* __restrict__ e) {
    int w = threadIdx.x >> 5, lane = threadIdx.x & 31;
    int n = blockIdx.x * 8 + w;
    float v[8];
    float ss = 0.f;
#pragma unroll
    for (int j = 0; j < 8; j++) {
        v[j] = e[(size_t)n * DD + j * 32 + lane];
        ss += v[j] * v[j];
    }
#pragma unroll
    for (int o = 16; o > 0; o >>= 1) ss += __shfl_xor_sync(0xffffffffu, ss, o);
    float inv = 1.f / fmaxf(sqrtf(ss), 1e-12f);
#pragma unroll
    for (int j = 0; j < 8; j++) {
        float h = v[j] * inv;
        g_ehat[(size_t)n * DD + j * 32 + lane] = h;
        g_eb[(size_t)n * DD + j * 32 + lane] = __float2bfloat16(h);
    }
}

// ---------------- HMMA bf16 GEMM with in-flight candidate capture ----------
// smem: A 64KB | B0 64KB | B1 64KB | rowmax 512B | margin 512B
#define SM_B0 65536
#define SM_B1 131072
#define SM_RM 196608
#define SM_MG 197120
#define DYN_SMEM (197120 + 512)

__global__ void __launch_bounds__(256) gemm_kernel() {
    extern __shared__ char sm[];
    uint32_t sA = s2u(sm);
    int tid = threadIdx.x, wid = tid >> 5, lane = tid & 31;
    int rb = blockIdx.x * 128;
    unsigned* rowmax_s = (unsigned*)(sm + SM_RM);
    float* marg_s = (float*)(sm + SM_MG);
    if (tid < 128) {
        rowmax_s[tid] = ford(-3.4e38f);
        // bound on bf16-input dot error (~0.004*||x||) with >2x slack
        marg_s[tid] = 0.01f * g_xnorm[rb + tid] + 0.02f;
    }

    // prologue: A tile (rows rb..rb+127) + B chunk 0
#pragma unroll
    for (int i = 0; i < 16; i++) {
        int q = tid + (i << 8);
        int row = q >> 5, u = q & 31;
        cpa16(sA + soff(row, u), g_xb + (size_t)(rb + row) * DD + u * 8);
        cpa16(sA + SM_B0 + soff(row, u), g_eb + (size_t)row * DD + u * 8);
    }
    CPA_COMMIT();
    CPA_WAIT0();
    __syncthreads();

    int wm = wid >> 2, wn = wid & 3;
    int g = lane >> 2, cpair = (lane & 3) * 2;

    // per-lane ldmatrix row/ku components
    int la7 = lane & 7;
    int rowA_c = wm * 64 + la7 + ((lane >> 3) & 1) * 8;  // + mi*16
    int kuA_c = (lane >> 4);
    int rowB_c = wn * 32 + la7 + ((lane >> 4) & 1) * 8;  // + h*16
    int kuB_c = (lane >> 3) & 1;

    for (int t = 0; t < 64; t++) {
        uint32_t sBc = sA + ((t & 1) ? SM_B1 : SM_B0);
        if (t < 63) {
            uint32_t sBn = sA + ((t & 1) ? SM_B0 : SM_B1);
            const __nv_bfloat16* gsrc = g_eb + (size_t)(t + 1) * 128 * DD;
#pragma unroll
            for (int i = 0; i < 16; i++) {
                int q = tid + (i << 8);
                int row = q >> 5, u = q & 31;
                cpa16(sBn + soff(row, u), gsrc + (size_t)row * DD + u * 8);
            }
            CPA_COMMIT();
        }

        float acc[4][4][4];
#pragma unroll
        for (int mi = 0; mi < 4; mi++)
#pragma unroll
            for (int ni = 0; ni < 4; ni++)
#pragma unroll
                for (int r = 0; r < 4; r++) acc[mi][ni][r] = 0.f;

#pragma unroll
        for (int ks = 0; ks < 16; ks++) {
            int kb = ks * 2;
            uint32_t b[4][2];
#pragma unroll
            for (int h = 0; h < 2; h++) {
                int rowB = rowB_c + h * 16;
                uint32_t addr = sBc + soff(rowB, kb + kuB_c);
                LDSM4(b[h * 2][0], b[h * 2][1], b[h * 2 + 1][0], b[h * 2 + 1][1],
                      addr);
            }
#pragma unroll
            for (int mi = 0; mi < 4; mi++) {
                int rowA = rowA_c + mi * 16;
                uint32_t addr = sA + soff(rowA, kb + kuA_c);
                uint32_t a0, a1, a2, a3;
                LDSM4(a0, a1, a2, a3, addr);
#pragma unroll
                for (int ni = 0; ni < 4; ni++)
                    MMA16816(acc[mi][ni], a0, a1, a2, a3, b[ni][0], b[ni][1]);
            }
        }

        // ---- phase A: per-row tile max -> smem rowmax (quad pre-reduced) ----
        float rmloc[8];
#pragma unroll
        for (int mi = 0; mi < 4; mi++) {
            float m0 = -3.4e38f, m1 = -3.4e38f;
#pragma unroll
            for (int ni = 0; ni < 4; ni++) {
                m0 = fmaxf(m0, fmaxf(acc[mi][ni][0], acc[mi][ni][1]));
                m1 = fmaxf(m1, fmaxf(acc[mi][ni][2], acc[mi][ni][3]));
            }
            rmloc[mi * 2] = m0;
            rmloc[mi * 2 + 1] = m1;
        }
#pragma unroll
        for (int s = 0; s < 8; s++) {
            float m = rmloc[s];
            m = fmaxf(m, __shfl_xor_sync(0xffffffffu, m, 1));
            m = fmaxf(m, __shfl_xor_sync(0xffffffffu, m, 2));
            rmloc[s] = m;                       // quad max (lanes share rows)
        }
        if ((lane & 3) == 0) {
#pragma unroll
            for (int s = 0; s < 8; s++) {
                int rl = wm * 64 + (s >> 1) * 16 + (s & 1) * 8 + g;
                atomicMax(&rowmax_s[rl], ford(rmloc[s]));
            }
        }
        if (t < 63) CPA_WAIT0();
        __syncthreads();   // rowmax visible to all; B prefetch landed

        // ---- phase B: append candidates above (rowmax - margin) ------------
        int ncol = t * 128 + wn * 32 + cpair;
#pragma unroll
        for (int mi = 0; mi < 4; mi++) {
#pragma unroll
            for (int half = 0; half < 2; half++) {
                int rl = wm * 64 + mi * 16 + half * 8 + g;
                float qm = rmloc[mi * 2 + half];
                float thr = unford(rowmax_s[rl]) - marg_s[rl];
                if (qm > thr) {
#pragma unroll
                    for (int ni = 0; ni < 4; ni++) {
                        float v0 = acc[mi][ni][half * 2];
                        float v1 = acc[mi][ni][half * 2 + 1];
                        if (v0 > thr) append_cand(rb + rl, ncol + ni * 8);
                        if (v1 > thr) append_cand(rb + rl, ncol + ni * 8 + 1);
                    }
                }
            }
        }
        // safe to let next iteration's prefetch overwrite the buffer we read:
        // every warp passed the barrier above after its last ldmatrix.
    }
}

// ---------------- exact fp32 rescore + fused epilogue ----------------------
__global__ void __launch_bounds__(256) rescore_kernel(const float* __restrict__ x,
                                                      const float* __restrict__ e,
                                                      float* __restrict__ out) {
    __shared__ float xs[256];
    __shared__ float wbv[8];
    __shared__ int wbi[8];
    __shared__ int idx_s;
    int b = blockIdx.x, t = threadIdx.x, w = t >> 5, lane = t & 31;

    xs[t] = x[(size_t)b * DD + t];
    __syncthreads();

    int c = g_ccnt[b];
    float bestv = -3.4e38f;
    int bestn = NN;
    const float4* xv4 = (const float4*)&xs[lane * 8];
    float4 x0 = xv4[0], x1 = xv4[1];

    if (c <= CAP) {
        for (int i = w; i < c; i += 8) {
            int n = g_cand[(size_t)b * CAP + i];
            const float4* ep = (const float4*)(g_ehat + (size_t)n * DD);
            float4 e0 = ep[lane * 2], e1 = ep[lane * 2 + 1];
            float p = x0.x * e0.x + x0.y * e0.y + x0.z * e0.z + x0.w * e0.w +
                      x1.x * e1.x + x1.y * e1.y + x1.z * e1.z + x1.w * e1.w;
#pragma unroll
            for (int o = 16; o > 0; o >>= 1)
                p += __shfl_xor_sync(0xffffffffu, p, o);
            if (p > bestv || (p == bestv && n < bestn)) { bestv = p; bestn = n; }
        }
    } else {
        // overflow fallback (provably correct, ~never taken): full fp32 row
        for (int n = w * (NN / 8); n < (w + 1) * (NN / 8); n++) {
            const float4* ep = (const float4*)(g_ehat + (size_t)n * DD);
            float4 e0 = ep[lane * 2], e1 = ep[lane * 2 + 1];
            float p = x0.x * e0.x + x0.y * e0.y + x0.z * e0.z + x0.w * e0.w +
                      x1.x * e1.x + x1.y * e1.y + x1.z * e1.z + x1.w * e1.w;
#pragma unroll
            for (int o = 16; o > 0; o >>= 1)
                p += __shfl_xor_sync(0xffffffffu, p, o);
            if (p > bestv || (p == bestv && n < bestn)) { bestv = p; bestn = n; }
        }
    }
    if (lane == 0) { wbv[w] = bestv; wbi[w] = bestn; }
    __syncthreads();
    if (t == 0) {
        float bv = -3.4e38f; int bi = NN;
#pragma unroll
        for (int i = 0; i < 8; i++) {
            if (wbv[i] > bv || (wbv[i] == bv && wbi[i] < bi)) {
                bv = wbv[i]; bi = wbi[i];
            }
        }
        idx_s = (bi == NN) ? 0 : bi;
    }
    __syncthreads();
    int idx = idx_s;

    // fused epilogue (same math as the passing round-1/3 kernels)
    float xvv = xs[t];
    float cv = e[(size_t)idx * DD + t];
    float s1 = xvv * cv, s2 = cv * cv, s3 = xvv * xvv;
#pragma unroll
    for (int o = 16; o > 0; o >>= 1) {
        s1 += __shfl_xor_sync(0xffffffffu, s1, o);
        s2 += __shfl_xor_sync(0xffffffffu, s2, o);
        s3 += __shfl_xor_sync(0xffffffffu, s3, o);
    }
    __shared__ float r1[8], r2[8], r3[8];
    __shared__ float bc[3];
    if (lane == 0) { r1[w] = s1; r2[w] = s2; r3[w] = s3; }
    __syncthreads();
    if (t == 0) {
        float d = 0.f, cc = 0.f, xx = 0.f;
#pragma unroll
        for (int i = 0; i < 8; i++) { d += r1[i]; cc += r2[i]; xx += r3[i]; }
        bc[0] = d; bc[1] = cc; bc[2] = xx;
    }
    __syncthreads();
    float dot = bc[0], csq = bc[1], xsq = bc[2];
    float scalar = dot / (csq + 1e-8f);
    float proj = scalar * cv;
    out[(size_t)b * DD + t] = xvv + (proj - xvv);
    if (t == 0) {
        float pn = fabsf(scalar) * sqrtf(csq);
        float commit = (scalar * dot) /
                       (fmaxf(pn, 1e-8f) * fmaxf(sqrtf(xsq), 1e-8f));
        g_commit[b] = 1.0f - commit;
        out[(size_t)BB * DD + 1 + b] = (float)idx;
        out[(size_t)BB * DD + 1 + BB + b] = scalar;
    }
}

// ---------------- loss -----------------------------------------------------
__global__ void loss_kernel(float* __restrict__ out) {
    __shared__ float sh[256];
    float s = 0.f;
    for (int i = threadIdx.x; i < BB; i += 256) s += g_commit[i];
    sh[threadIdx.x] = s;
    __syncthreads();
    for (int o = 128; o > 0; o >>= 1) {
        if (threadIdx.x < o) sh[threadIdx.x] += sh[threadIdx.x + o];
        __syncthreads();
    }
    if (threadIdx.x == 0) out[(size_t)BB * DD] = 0.25f * sh[0] / (float)BB;
}

// ---------------------------------------------------------------------------
extern "C" void kernel_launch(void* const* d_in, const int* in_sizes, int n_in,
                              void* d_out, int out_size) {
    const float* x = (const float*)d_in[0];
    const float* e = (const float*)d_in[1];
    float* out = (float*)d_out;

    cudaFuncSetAttribute(gemm_kernel,
                         cudaFuncAttributeMaxDynamicSharedMemorySize, DYN_SMEM);
    prep_x_kernel<<<BB / 8, 256>>>(x);
    prep_e_kernel<<<NN / 8, 256>>>(e);
    gemm_kernel<<<BB / 128, 256, DYN_SMEM>>>();
    rescore_kernel<<<BB, 256>>>(x, e, out);
    loss_kernel<<<1, 256>>>(out);
}